// round 16
// baseline (speedup 1.0000x reference)
#include <cuda_runtime.h>
#include <cstdint>
#include <cmath>

// SlidingGaussianWindow1d: out[b,w,c,d] = clip(corrcoef_t of x[b,t,:] * W[w,t])
// B=16, T=256, C=64, NWIN=224.
//
// Identities:
//  - W[w,t] = A[(t + S_w) mod 256], S_w = (w+1)(w-222)/2
//  - A = conv(gauss, box)/max is INDEPENDENT of win_alpha -> host-computed,
//    passed as a 1KB kernel parameter (constant-bank broadcast reads).
//  - A ~0 outside a ~40-wide arc: t-loop truncated to the support.
//  - corr_cd = (S_cd - m_c m_d/T) * dinv_c * dinv_d (1/(T-1) cancels)
//  - Split y = hi + lo (bf16):  S ~= HtH + HtL + LtH,  and LtH = (HtL)^T
//    -> TWO mma chains (C1 = HtH, C2 = HtL); S = C1 + C2 + C2^T via the
//    smem staging tile (transposed reads are conflict-free at stride 68).
//
// R16: 2-chain mainloop (48 mma, 6 ldmatrix per k-step), C2-transpose
// epilogue, occupancy 9 (aL operand freed 8 regs).

#define T_LEN 256
#define C_DIM 64
#define NWIN  224
#define B_DIM 16
#define KCH   48            // K capacity of operand buffers (48 k, zero-padded)
#define HSTB  112           // Ht/Lt row stride in bytes (16B-aligned, 7x16)
#define CBW   68            // staging tile row stride in words (272B)

struct WinParam {
    float A[256];
    int   ilo;
    int   keff;
};

// ---------------------------------------------------------------------------
__device__ __forceinline__ void mma_bf16(float* d, const uint32_t* a, const uint32_t* b) {
    asm volatile(
        "mma.sync.aligned.m16n8k16.row.col.f32.bf16.bf16.f32 "
        "{%0,%1,%2,%3}, {%4,%5,%6,%7}, {%8,%9}, {%0,%1,%2,%3};"
        : "+f"(d[0]), "+f"(d[1]), "+f"(d[2]), "+f"(d[3])
        : "r"(a[0]), "r"(a[1]), "r"(a[2]), "r"(a[3]), "r"(b[0]), "r"(b[1]));
}
__device__ __forceinline__ void ldmx4(uint32_t* r, uint32_t addr) {
    asm volatile("ldmatrix.sync.aligned.m8n8.x4.shared.b16 {%0,%1,%2,%3}, [%4];"
                 : "=r"(r[0]), "=r"(r[1]), "=r"(r[2]), "=r"(r[3]) : "r"(addr));
}
__device__ __forceinline__ void sts128(uint32_t addr, uint32_t v0, uint32_t v1,
                                       uint32_t v2, uint32_t v3) {
    asm volatile("st.shared.v4.b32 [%0], {%1,%2,%3,%4};"
                 :: "r"(addr), "r"(v0), "r"(v1), "r"(v2), "r"(v3));
}

// ---------------------------------------------------------------------------
// 128 threads per (w, b). Warp grid 2x2: warp wid owns the
// (m32 = (wid&1)*32, n32 = (wid>>1)*32) block of S.
// Operands Ht/Lt: bf16 [c][k] rows, stride 112B, built straight from gmem.
// NKS = number of k16 steps (keff <= 16*NKS <= 48), compile-time.
// ---------------------------------------------------------------------------
template <int NKS>
__global__ __launch_bounds__(128, 9) void corr_tmpl(const float* __restrict__ x,
                                                    float* __restrict__ out,
                                                    const __grid_constant__ WinParam wp) {
    // union: [mma] Ht(7168B)+Lt(7168B) | [epilogue] 64x68-word tile (C2, then corr)
    __shared__ __align__(16) uint32_t SMEMU[64 * CBW];   // 17408 B
    __shared__ float mpart[2][64];
    __shared__ float mcol[64];
    __shared__ float dinv[64];

    const int w    = blockIdx.x;
    const int b    = blockIdx.y;
    const int tid  = threadIdx.x;
    const int wid  = tid >> 5;
    const int lane = tid & 31;
    const int g    = lane >> 2;          // fragment group row (0..7)
    const int tig  = lane & 3;           // thread-in-group

    int s = ((w + 1) * (w - 222)) / 2;   // cumulative roll (even product, exact)
    int smod = ((s % 256) + 256) & 255;

    const int ilo = wp.ilo;
    const int jn  = wp.keff;             // <= 16*NKS

    const float* xb = x + ((size_t)b << 14);
    const int mb = (wid & 1) << 5;       // warp m-base (rows of S)
    const int nb = (wid >> 1) << 5;      // warp n-base (cols of S)

    const uint32_t htb = (uint32_t)__cvta_generic_to_shared(&SMEMU[0]);
    const uint32_t ltb = htb + (uint32_t)(16 * HSTB * 4);   // 7168 B
    const uint32_t LH  = ltb - htb;

    // ldmatrix per-lane offsets (bytes) into the [c][k] buffers.
    const int matA = lane >> 3;
    const uint32_t offA0 = (uint32_t)((mb + (lane & 7) + (matA & 1) * 8) * HSTB
                                      + (matA >> 1) * 16);
    const uint32_t offB0 = (uint32_t)((nb + (lane & 7) + (lane >> 4) * 8) * HSTB
                                      + ((lane >> 3) & 1) * 16);

    float D1[2][4][4];                   // H^T H
    float D2[2][4][4];                   // H^T L
    #pragma unroll
    for (int mt = 0; mt < 2; mt++)
        #pragma unroll
        for (int nt = 0; nt < 4; nt++)
            #pragma unroll
            for (int e = 0; e < 4; e++) { D1[mt][nt][e] = 0.0f; D2[mt][nt][e] = 0.0f; }
    float msum = 0.0f;

    // build mapping: thread owns row csp, k-half ksp (24 k each)
    const int csp = tid & 63;
    const int ksp = tid >> 6;

    // ---- build Ht/Lt from gmem; packed 16B stores; A via constant bank ----
    {
        int t0 = (ilo - smod) & 255;
        uint32_t hdst = htb + csp * HSTB + ksp * 48;
        #pragma unroll
        for (int g3 = 0; g3 < 3; g3++) {
            int k0 = ksp * 24 + g3 * 8;
            float y[8];
            #pragma unroll
            for (int u = 0; u < 8; u++) {
                int j = k0 + u;
                float v = 0.0f;
                if (j < jn) {
                    int t = (t0 + j) & 255;
                    v = xb[(t << 6) + csp] * wp.A[ilo + j];
                }
                y[u] = v;
                msum += v;
            }
            uint32_t hp[4], lp[4];
            #pragma unroll
            for (int v2 = 0; v2 < 4; v2++) {
                float y0 = y[2 * v2], y1 = y[2 * v2 + 1];
                uint32_t hpv;
                asm("cvt.rn.bf16x2.f32 %0, %1, %2;" : "=r"(hpv) : "f"(y1), "f"(y0));
                float h0 = __uint_as_float(hpv << 16);
                float h1 = __uint_as_float(hpv & 0xFFFF0000u);
                float l0 = y0 - h0;
                float l1 = y1 - h1;
                uint32_t lpv;
                asm("cvt.rn.bf16x2.f32 %0, %1, %2;" : "=r"(lpv) : "f"(l1), "f"(l0));
                hp[v2] = hpv;
                lp[v2] = lpv;
            }
            sts128(hdst + g3 * 16,      hp[0], hp[1], hp[2], hp[3]);
            sts128(hdst + LH + g3 * 16, lp[0], lp[1], lp[2], lp[3]);
        }
    }
    __syncthreads();

    // ---- mma mainloop: 2 chains, fully unrolled ----
    #pragma unroll
    for (int ks = 0; ks < NKS; ks++) {
        uint32_t ko = (uint32_t)(ks << 5);   // 16 k * 2B
        uint32_t aH[2][4];
        ldmx4(aH[0], htb + offA0 + ko);
        ldmx4(aH[1], htb + offA0 + (uint32_t)(16 * HSTB) + ko);
        #pragma unroll
        for (int bt = 0; bt < 2; bt++) {
            uint32_t bo = offB0 + (uint32_t)(bt * 16 * HSTB) + ko;
            uint32_t bh[4], bl[4];
            ldmx4(bh, htb + bo);
            ldmx4(bl, ltb + bo);
            #pragma unroll
            for (int mt = 0; mt < 2; mt++) {
                #pragma unroll
                for (int pr = 0; pr < 2; pr++) {
                    mma_bf16(D1[mt][bt * 2 + pr], aH[mt], bh + 2 * pr);  // H^T H
                    mma_bf16(D2[mt][bt * 2 + pr], aH[mt], bl + 2 * pr);  // H^T L
                }
            }
        }
    }

    // ---- column sums partials ----
    mpart[ksp][csp] = msum;
    __syncthreads();                     // operand reads done; tile reusable

    // ---- stage C2 = D2 into tile [c][d]; combine mcol ----
    float* cb = (float*)SMEMU;
    #pragma unroll
    for (int mt = 0; mt < 2; mt++) {
        #pragma unroll
        for (int rh = 0; rh < 2; rh++) {
            int c = mb + mt * 16 + rh * 8 + g;
            #pragma unroll
            for (int nt = 0; nt < 4; nt++) {
                int d = nb + nt * 8 + (tig << 1);
                float2 v = make_float2(D2[mt][nt][rh * 2], D2[mt][nt][rh * 2 + 1]);
                *(float2*)(cb + c * CBW + d) = v;
            }
        }
    }
    if (tid < 64) mcol[tid] = mpart[0][tid] + mpart[1][tid];
    __syncthreads();

    // ---- dinv from own regs (S_cc = C1_cc + 2*C2_cc); C2T combine into D1 ----
    const float inv256 = 1.0f / 256.0f;
    if (mb == nb && tig == (g >> 1)) {
        #pragma unroll
        for (int mt = 0; mt < 2; mt++) {
            #pragma unroll
            for (int rh = 0; rh < 2; rh++) {
                int c = mb + mt * 16 + rh * 8 + g;
                int nt = mt * 2 + rh;
                int e  = (g & 1) + rh * 2;
                float m = mcol[c];
                dinv[c] = rsqrtf(D1[mt][nt][e] + 2.0f * D2[mt][nt][e] - m * m * inv256);
            }
        }
    }
    // Sraw = C1 + C2 + C2^T - m_c m_d /256   (C2^T read conflict-free)
    #pragma unroll
    for (int mt = 0; mt < 2; mt++) {
        #pragma unroll
        for (int rh = 0; rh < 2; rh++) {
            int c = mb + mt * 16 + rh * 8 + g;
            float mc = mcol[c] * inv256;
            #pragma unroll
            for (int nt = 0; nt < 4; nt++) {
                #pragma unroll
                for (int ee = 0; ee < 2; ee++) {
                    int d = nb + nt * 8 + (tig << 1) + ee;
                    int e = rh * 2 + ee;
                    float c2t = cb[d * CBW + c];
                    D1[mt][nt][e] = D1[mt][nt][e] + D2[mt][nt][e] + c2t - mc * mcol[d];
                }
            }
        }
    }
    __syncthreads();                     // all C2 reads done; dinv ready

    // ---- normalize + clip into tile (overwrite C2) ----
    #pragma unroll
    for (int mt = 0; mt < 2; mt++) {
        #pragma unroll
        for (int rh = 0; rh < 2; rh++) {
            int c = mb + mt * 16 + rh * 8 + g;
            float dc = dinv[c];
            #pragma unroll
            for (int nt = 0; nt < 4; nt++) {
                int d = nb + nt * 8 + (tig << 1);
                float2 v;
                v.x = D1[mt][nt][rh * 2 + 0] * dc * dinv[d];
                v.y = D1[mt][nt][rh * 2 + 1] * dc * dinv[d + 1];
                v.x = fminf(1.0f, fmaxf(-1.0f, v.x));
                v.y = fminf(1.0f, fmaxf(-1.0f, v.y));
                *(float2*)(cb + c * CBW + d) = v;
            }
        }
    }
    __syncthreads();

    // ---- stream out: full coalesced rows, 512B per warp op ----
    float* ob = out + (((size_t)(b * NWIN + w)) << 12);
    #pragma unroll
    for (int p = 0; p < 8; p++) {
        int idx = (p << 7) + tid;        // 0..1023 float4 slots
        int r   = idx >> 4;
        int c4  = (idx & 15) << 2;
        float4 v = *(float4*)(cb + r * CBW + c4);
        *(float4*)(ob + (r << 6) + c4) = v;
    }
}

// ---------------------------------------------------------------------------
// Fallback: generic chunked kernel (keff > 48; not hit for alpha=0.5).
// ---------------------------------------------------------------------------
__global__ __launch_bounds__(128, 8) void corr_gen(const float* __restrict__ x,
                                                   float* __restrict__ out,
                                                   const __grid_constant__ WinParam wp) {
    __shared__ __align__(16) uint32_t Hts[(64 * HSTB) / 4];
    __shared__ __align__(16) uint32_t Lts[(64 * HSTB) / 4];
    __shared__ float mpart[2][64];
    __shared__ float mcol[64];
    __shared__ float dinv[64];

    const int w    = blockIdx.x;
    const int b    = blockIdx.y;
    const int tid  = threadIdx.x;
    const int wid  = tid >> 5;
    const int lane = tid & 31;
    const int g    = lane >> 2;
    const int tig  = lane & 3;

    int s = ((w + 1) * (w - 222)) / 2;
    int smod = ((s % 256) + 256) & 255;
    const int ilo  = wp.ilo;
    const int keff = wp.keff;

    const float* xb = x + ((size_t)b << 14);
    const int mb = (wid & 1) << 5;
    const int nb = (wid >> 1) << 5;

    const uint32_t htb = (uint32_t)__cvta_generic_to_shared(&Hts[0]);
    const uint32_t ltb = (uint32_t)__cvta_generic_to_shared(&Lts[0]);
    const uint32_t LH  = ltb - htb;

    const int matA = lane >> 3;
    const uint32_t offA0 = (uint32_t)((mb + (lane & 7) + (matA & 1) * 8) * HSTB
                                      + (matA >> 1) * 16);
    const uint32_t offB0 = (uint32_t)((nb + (lane & 7) + (lane >> 4) * 8) * HSTB
                                      + ((lane >> 3) & 1) * 16);

    float D[2][4][4];
    #pragma unroll
    for (int mt = 0; mt < 2; mt++)
        #pragma unroll
        for (int nt = 0; nt < 4; nt++)
            #pragma unroll
            for (int e = 0; e < 4; e++) D[mt][nt][e] = 0.0f;
    float msum = 0.0f;

    const int csp = tid & 63;
    const int ksp = tid >> 6;

    for (int base = 0; base < keff; base += KCH) {
        int jn = keff - base; if (jn > KCH) jn = KCH;
        if (base) __syncthreads();
        {
            int t0 = (ilo + base - smod) & 255;
            uint32_t hdst = htb + csp * HSTB + ksp * 48;
            #pragma unroll
            for (int g3 = 0; g3 < 3; g3++) {
                int k0 = ksp * 24 + g3 * 8;
                float y[8];
                #pragma unroll
                for (int u = 0; u < 8; u++) {
                    int j = k0 + u;
                    float v = 0.0f;
                    if (j < jn) {
                        int t = (t0 + j) & 255;
                        v = xb[(t << 6) + csp] * wp.A[ilo + base + j];
                    }
                    y[u] = v;
                    msum += v;
                }
                uint32_t hp[4], lp[4];
                #pragma unroll
                for (int v2 = 0; v2 < 4; v2++) {
                    float y0 = y[2 * v2], y1 = y[2 * v2 + 1];
                    uint32_t hpv;
                    asm("cvt.rn.bf16x2.f32 %0, %1, %2;" : "=r"(hpv) : "f"(y1), "f"(y0));
                    float h0 = __uint_as_float(hpv << 16);
                    float h1 = __uint_as_float(hpv & 0xFFFF0000u);
                    float l0 = y0 - h0;
                    float l1 = y1 - h1;
                    uint32_t lpv;
                    asm("cvt.rn.bf16x2.f32 %0, %1, %2;" : "=r"(lpv) : "f"(l1), "f"(l0));
                    hp[v2] = hpv;
                    lp[v2] = lpv;
                }
                sts128(hdst + g3 * 16,      hp[0], hp[1], hp[2], hp[3]);
                sts128(hdst + LH + g3 * 16, lp[0], lp[1], lp[2], lp[3]);
            }
        }
        __syncthreads();

        int nks = (jn + 15) >> 4;
        #pragma unroll 3
        for (int ks = 0; ks < nks; ks++) {
            uint32_t ko = (uint32_t)(ks << 5);
            uint32_t aH[2][4], aL[2][4];
            ldmx4(aH[0], htb + offA0 + ko);
            ldmx4(aH[1], htb + offA0 + (uint32_t)(16 * HSTB) + ko);
            ldmx4(aL[0], ltb + offA0 + ko);
            ldmx4(aL[1], ltb + offA0 + (uint32_t)(16 * HSTB) + ko);
            #pragma unroll
            for (int bt = 0; bt < 2; bt++) {
                uint32_t bo = offB0 + (uint32_t)(bt * 16 * HSTB) + ko;
                uint32_t bh[4], bl[4];
                ldmx4(bh, htb + bo);
                ldmx4(bl, ltb + bo);
                #pragma unroll
                for (int mt = 0; mt < 2; mt++) {
                    #pragma unroll
                    for (int pr = 0; pr < 2; pr++) {
                        float* Dp = D[mt][bt * 2 + pr];
                        mma_bf16(Dp, aH[mt], bh + 2 * pr);
                        mma_bf16(Dp, aH[mt], bl + 2 * pr);
                        mma_bf16(Dp, aL[mt], bh + 2 * pr);
                    }
                }
            }
        }
    }

    mpart[ksp][csp] = msum;
    __syncthreads();
    if (tid < 64) mcol[tid] = mpart[0][tid] + mpart[1][tid];
    __syncthreads();

    const float inv256 = 1.0f / 256.0f;
    if (mb == nb && tig == (g >> 1)) {
        #pragma unroll
        for (int mt = 0; mt < 2; mt++) {
            #pragma unroll
            for (int rh = 0; rh < 2; rh++) {
                int c = mb + mt * 16 + rh * 8 + g;
                int nt = mt * 2 + rh;
                int e  = (g & 1) + rh * 2;
                float m = mcol[c];
                dinv[c] = rsqrtf(D[mt][nt][e] - m * m * inv256);
            }
        }
    }
    __syncthreads();

    float* ob = out + (((size_t)(b * NWIN + w)) << 12);
    const int d0 = nb + (tig << 1);
    #pragma unroll
    for (int mt = 0; mt < 2; mt++) {
        #pragma unroll
        for (int rh = 0; rh < 2; rh++) {
            int c = mb + mt * 16 + rh * 8 + g;
            float mc = mcol[c] * inv256;
            float dc = dinv[c];
            #pragma unroll
            for (int nt = 0; nt < 4; nt++) {
                int d = d0 + nt * 8;
                float md0 = mcol[d], md1 = mcol[d + 1];
                float dd0 = dinv[d], dd1 = dinv[d + 1];
                float2 v;
                v.x = (D[mt][nt][rh * 2 + 0] - mc * md0) * dc * dd0;
                v.y = (D[mt][nt][rh * 2 + 1] - mc * md1) * dc * dd1;
                v.x = fminf(1.0f, fmaxf(-1.0f, v.x));
                v.y = fminf(1.0f, fmaxf(-1.0f, v.y));
                *(float2*)(ob + (c << 6) + d) = v;
            }
        }
    }
}

// ---------------------------------------------------------------------------
// Host: window table (alpha-independent; scale cancels in normalization).
// ---------------------------------------------------------------------------
extern "C" void kernel_launch(void* const* d_in, const int* in_sizes, int n_in,
                              void* d_out, int out_size) {
    const float* x = (const float*)d_in[0];       // (16, 256, 64) fp32
    float* out = (float*)d_out;                   // (16, 224, 64, 64) fp32

    WinParam wp;
    {
        double gw[256], P[256];
        double acc = 0.0;
        for (int t = 0; t < 256; t++) {
            double d = (double)t - 128.0;
            gw[t] = exp(-d * d);
            acc += gw[t];
            P[t] = acc;
        }
        double Ac[511];
        double mx = 0.0;
        for (int n = 0; n < 511; n++) {
            double v = 0.0;
            if (n >= 112 && n <= 398) {
                int hi = n - 112; if (hi > 255) hi = 255;
                double ph = P[hi];
                double pl = (n >= 144) ? P[n - 144] : 0.0;
                v = ph - pl;
            }
            Ac[n] = v;
            if (v > mx) mx = v;
        }
        int lo = 255, hi = 0;
        for (int t = 0; t < 256; t++) {
            double a = Ac[128 + t] / mx;
            wp.A[t] = (float)a;
            if (a > 1e-6) { if (t < lo) lo = t; if (t > hi) hi = t; }
        }
        if (hi < lo) { lo = 0; hi = 255; }
        wp.ilo  = lo;
        wp.keff = hi - lo + 1;
    }

    dim3 grid(NWIN, B_DIM);
    if (wp.keff <= 16)      corr_tmpl<1><<<grid, 128>>>(x, out, wp);
    else if (wp.keff <= 32) corr_tmpl<2><<<grid, 128>>>(x, out, wp);
    else if (wp.keff <= 48) corr_tmpl<3><<<grid, 128>>>(x, out, wp);
    else                    corr_gen<<<grid, 128>>>(x, out, wp);
}

// round 17
// speedup vs baseline: 2.9444x; 2.9444x over previous
#include <cuda_runtime.h>
#include <cstdint>
#include <cmath>

// SlidingGaussianWindow1d: out[b,w,c,d] = clip(corrcoef_t of x[b,t,:] * W[w,t])
// B=16, T=256, C=64, NWIN=224.
//
// Identities:
//  - W[w,t] = A[(t + S_w) mod 256], S_w = (w+1)(w-222)/2
//  - A = conv(gauss, box)/max is INDEPENDENT of win_alpha -> host-computed,
//    passed as a 1KB kernel parameter (constant-bank broadcast reads).
//  - A ~0 outside a ~40-wide arc: t-loop truncated to the support.
//  - corr_cd = (S_cd - m_c m_d/T) * dinv_c * dinv_d (1/(T-1) cancels)
//
// R17: 256-thread CTA, 2x4 warp grid (warp = m32 x n16, 16 accum regs) ->
// launch_bounds(256,5): 40 warps/SM vs 31, for the latency-bound regime.
// 3-chain split-Gram mma (S ~= HtH + HtL + LtH) as in R15 (proven numerics).

#define T_LEN 256
#define C_DIM 64
#define NWIN  224
#define B_DIM 16
#define KCH   48            // K capacity of operand buffers (48 k, zero-padded)
#define HSTB  112           // Ht/Lt row stride in bytes (16B-aligned, 7x16)
#define CBW   68            // staging tile row stride in words (272B)

struct WinParam {
    float A[256];
    int   ilo;
    int   keff;
};

// ---------------------------------------------------------------------------
__device__ __forceinline__ void mma_bf16(float* d, const uint32_t* a, const uint32_t* b) {
    asm volatile(
        "mma.sync.aligned.m16n8k16.row.col.f32.bf16.bf16.f32 "
        "{%0,%1,%2,%3}, {%4,%5,%6,%7}, {%8,%9}, {%0,%1,%2,%3};"
        : "+f"(d[0]), "+f"(d[1]), "+f"(d[2]), "+f"(d[3])
        : "r"(a[0]), "r"(a[1]), "r"(a[2]), "r"(a[3]), "r"(b[0]), "r"(b[1]));
}
__device__ __forceinline__ void ldmx4(uint32_t* r, uint32_t addr) {
    asm volatile("ldmatrix.sync.aligned.m8n8.x4.shared.b16 {%0,%1,%2,%3}, [%4];"
                 : "=r"(r[0]), "=r"(r[1]), "=r"(r[2]), "=r"(r[3]) : "r"(addr));
}
__device__ __forceinline__ void sts64(uint32_t addr, uint32_t v0, uint32_t v1) {
    asm volatile("st.shared.v2.b32 [%0], {%1,%2};" :: "r"(addr), "r"(v0), "r"(v1));
}
__device__ __forceinline__ void sts128(uint32_t addr, uint32_t v0, uint32_t v1,
                                       uint32_t v2, uint32_t v3) {
    asm volatile("st.shared.v4.b32 [%0], {%1,%2,%3,%4};"
                 :: "r"(addr), "r"(v0), "r"(v1), "r"(v2), "r"(v3));
}
__device__ __forceinline__ uint32_t bf16pair(float y0, float y1) {
    uint32_t p;
    asm("cvt.rn.bf16x2.f32 %0, %1, %2;" : "=r"(p) : "f"(y1), "f"(y0));
    return p;
}

// ---------------------------------------------------------------------------
// 256 threads per (w, b). Warp grid 2x4: warp wid: mi = wid&1, ni = wid>>1;
// owns (m32 = 32*mi, n16 = 16*ni) block of S. 3 mma chains: HH, HL, LH.
// Operands Ht/Lt: bf16 [c][k] rows, stride 112B, built straight from gmem.
// NKS = number of k16 steps (keff <= 16*NKS <= 48), compile-time.
// ---------------------------------------------------------------------------
template <int NKS>
__global__ __launch_bounds__(256, 5) void corr_tmpl(const float* __restrict__ x,
                                                    float* __restrict__ out,
                                                    const __grid_constant__ WinParam wp) {
    // union: [mma] Ht(7168B)+Lt(7168B) | [epilogue] 64x68-word corr tile
    __shared__ __align__(16) uint32_t SMEMU[64 * CBW];   // 17408 B
    __shared__ float mpart[4][64];
    __shared__ float mcol[64];
    __shared__ float dinv[64];
    __shared__ float sdraw[64];

    const int w    = blockIdx.x;
    const int b    = blockIdx.y;
    const int tid  = threadIdx.x;
    const int wid  = tid >> 5;
    const int lane = tid & 31;
    const int g    = lane >> 2;          // fragment group row (0..7)
    const int tig  = lane & 3;           // thread-in-group

    int s = ((w + 1) * (w - 222)) / 2;   // cumulative roll (even product, exact)
    int smod = ((s % 256) + 256) & 255;

    const int ilo = wp.ilo;
    const int jn  = wp.keff;             // <= 16*NKS

    const float* xb = x + ((size_t)b << 14);
    const int mb = (wid & 1) << 5;       // warp m-base (rows of S)
    const int nb = (wid >> 1) << 4;      // warp n-base (cols of S), 16-wide

    const uint32_t htb = (uint32_t)__cvta_generic_to_shared(&SMEMU[0]);
    const uint32_t ltb = htb + (uint32_t)(16 * HSTB * 4);   // 7168 B
    const uint32_t LH  = ltb - htb;

    // ldmatrix per-lane offsets (bytes) into the [c][k] buffers.
    const int matA = lane >> 3;
    const uint32_t offA0 = (uint32_t)((mb + (lane & 7) + (matA & 1) * 8) * HSTB
                                      + (matA >> 1) * 16);
    // B n16k16: matrices {n0k0, n0k8, n8k0, n8k8}
    const uint32_t offB0 = (uint32_t)((nb + (lane & 7) + (lane >> 4) * 8) * HSTB
                                      + ((lane >> 3) & 1) * 16);

    float D[2][2][4];                    // [mt][pr][e]: full S block accum
    #pragma unroll
    for (int mt = 0; mt < 2; mt++)
        #pragma unroll
        for (int pr = 0; pr < 2; pr++)
            #pragma unroll
            for (int e = 0; e < 4; e++) D[mt][pr][e] = 0.0f;
    float msum = 0.0f;

    // build mapping: thread owns row csp, k-quarter kq (12 k each)
    const int csp = tid & 63;
    const int kq  = tid >> 6;            // 0..3

    // ---- build Ht/Lt from gmem; A via constant bank; 8B packed stores ----
    {
        int t0 = (ilo - smod) & 255;
        uint32_t hdst = htb + csp * HSTB + kq * 24;
        #pragma unroll
        for (int g3 = 0; g3 < 3; g3++) {
            int k0 = kq * 12 + g3 * 4;
            float y[4];
            #pragma unroll
            for (int u = 0; u < 4; u++) {
                int j = k0 + u;
                float v = 0.0f;
                if (j < jn) {
                    int t = (t0 + j) & 255;
                    v = xb[(t << 6) + csp] * wp.A[ilo + j];
                }
                y[u] = v;
                msum += v;
            }
            uint32_t hp0 = bf16pair(y[0], y[1]);
            uint32_t hp1 = bf16pair(y[2], y[3]);
            float l0 = y[0] - __uint_as_float(hp0 << 16);
            float l1 = y[1] - __uint_as_float(hp0 & 0xFFFF0000u);
            float l2 = y[2] - __uint_as_float(hp1 << 16);
            float l3 = y[3] - __uint_as_float(hp1 & 0xFFFF0000u);
            uint32_t lp0 = bf16pair(l0, l1);
            uint32_t lp1 = bf16pair(l2, l3);
            sts64(hdst + g3 * 8,      hp0, hp1);
            sts64(hdst + LH + g3 * 8, lp0, lp1);
        }
    }
    __syncthreads();

    // ---- mma mainloop: fully unrolled, NKS k-steps ----
    #pragma unroll
    for (int ks = 0; ks < NKS; ks++) {
        uint32_t ko = (uint32_t)(ks << 5);   // 16 k * 2B
        uint32_t aH[2][4], aL[2][4], bh[4], bl[4];
        ldmx4(aH[0], htb + offA0 + ko);
        ldmx4(aH[1], htb + offA0 + (uint32_t)(16 * HSTB) + ko);
        ldmx4(bh, htb + offB0 + ko);
        ldmx4(bl, ltb + offB0 + ko);
        #pragma unroll
        for (int mt = 0; mt < 2; mt++) {
            #pragma unroll
            for (int pr = 0; pr < 2; pr++) {
                mma_bf16(D[mt][pr], aH[mt], bh + 2 * pr);    // H^T H
                mma_bf16(D[mt][pr], aH[mt], bl + 2 * pr);    // H^T L
            }
        }
        ldmx4(aL[0], ltb + offA0 + ko);
        ldmx4(aL[1], ltb + offA0 + (uint32_t)(16 * HSTB) + ko);
        #pragma unroll
        for (int mt = 0; mt < 2; mt++) {
            #pragma unroll
            for (int pr = 0; pr < 2; pr++) {
                mma_bf16(D[mt][pr], aL[mt], bh + 2 * pr);    // L^T H
            }
        }
    }

    // ---- publish column-sum partials + raw diagonal values ----
    mpart[kq][csp] = msum;
    #pragma unroll
    for (int mt = 0; mt < 2; mt++)
        #pragma unroll
        for (int pr = 0; pr < 2; pr++)
            #pragma unroll
            for (int rh = 0; rh < 2; rh++)
                #pragma unroll
                for (int ee = 0; ee < 2; ee++) {
                    int c = mb + mt * 16 + rh * 8 + g;
                    int d = nb + pr * 8 + (tig << 1) + ee;
                    if (c == d) sdraw[c] = D[mt][pr][rh * 2 + ee];
                }
    __syncthreads();

    // ---- mcol + dinv in one step ----
    const float inv256 = 1.0f / 256.0f;
    if (tid < 64) {
        float m = mpart[0][tid] + mpart[1][tid] + mpart[2][tid] + mpart[3][tid];
        mcol[tid] = m;
        dinv[tid] = rsqrtf(sdraw[tid] - m * m * inv256);
    }
    __syncthreads();

    // ---- normalize + clip into staging tile ----
    float* cb = (float*)SMEMU;           // union reuse: mma reads complete
    #pragma unroll
    for (int mt = 0; mt < 2; mt++) {
        #pragma unroll
        for (int rh = 0; rh < 2; rh++) {
            int c = mb + mt * 16 + rh * 8 + g;
            float mc = mcol[c] * inv256;
            float dc = dinv[c];
            #pragma unroll
            for (int pr = 0; pr < 2; pr++) {
                int d = nb + pr * 8 + (tig << 1);
                float2 v;
                v.x = (D[mt][pr][rh * 2 + 0] - mc * mcol[d])     * dc * dinv[d];
                v.y = (D[mt][pr][rh * 2 + 1] - mc * mcol[d + 1]) * dc * dinv[d + 1];
                v.x = fminf(1.0f, fmaxf(-1.0f, v.x));
                v.y = fminf(1.0f, fmaxf(-1.0f, v.y));
                *(float2*)(cb + c * CBW + d) = v;
            }
        }
    }
    __syncthreads();

    // ---- stream out: full coalesced rows, 4 passes of 256 float4 ----
    float* ob = out + (((size_t)(b * NWIN + w)) << 12);
    #pragma unroll
    for (int p = 0; p < 4; p++) {
        int idx = (p << 8) + tid;        // 0..1023 float4 slots
        int r   = idx >> 4;
        int c4  = (idx & 15) << 2;
        float4 v = *(float4*)(cb + r * CBW + c4);
        *(float4*)(ob + (r << 6) + c4) = v;
    }
}

// ---------------------------------------------------------------------------
// Fallback: generic chunked kernel (keff > 48; not hit for alpha=0.5).
// ---------------------------------------------------------------------------
__global__ __launch_bounds__(128, 8) void corr_gen(const float* __restrict__ x,
                                                   float* __restrict__ out,
                                                   const __grid_constant__ WinParam wp) {
    __shared__ __align__(16) uint32_t Hts[(64 * HSTB) / 4];
    __shared__ __align__(16) uint32_t Lts[(64 * HSTB) / 4];
    __shared__ float mpart[2][64];
    __shared__ float mcol[64];
    __shared__ float dinv[64];

    const int w    = blockIdx.x;
    const int b    = blockIdx.y;
    const int tid  = threadIdx.x;
    const int wid  = tid >> 5;
    const int lane = tid & 31;
    const int g    = lane >> 2;
    const int tig  = lane & 3;

    int s = ((w + 1) * (w - 222)) / 2;
    int smod = ((s % 256) + 256) & 255;
    const int ilo  = wp.ilo;
    const int keff = wp.keff;

    const float* xb = x + ((size_t)b << 14);
    const int mb = (wid & 1) << 5;
    const int nb = (wid >> 1) << 5;

    const uint32_t htb = (uint32_t)__cvta_generic_to_shared(&Hts[0]);
    const uint32_t ltb = (uint32_t)__cvta_generic_to_shared(&Lts[0]);
    const uint32_t LH  = ltb - htb;

    const int matA = lane >> 3;
    const uint32_t offA0 = (uint32_t)((mb + (lane & 7) + (matA & 1) * 8) * HSTB
                                      + (matA >> 1) * 16);
    const uint32_t offB0 = (uint32_t)((nb + (lane & 7) + (lane >> 4) * 8) * HSTB
                                      + ((lane >> 3) & 1) * 16);

    float D[2][4][4];
    #pragma unroll
    for (int mt = 0; mt < 2; mt++)
        #pragma unroll
        for (int nt = 0; nt < 4; nt++)
            #pragma unroll
            for (int e = 0; e < 4; e++) D[mt][nt][e] = 0.0f;
    float msum = 0.0f;

    const int csp = tid & 63;
    const int ksp = tid >> 6;

    for (int base = 0; base < keff; base += KCH) {
        int jn = keff - base; if (jn > KCH) jn = KCH;
        if (base) __syncthreads();
        {
            int t0 = (ilo + base - smod) & 255;
            uint32_t hdst = htb + csp * HSTB + ksp * 48;
            #pragma unroll
            for (int g3 = 0; g3 < 3; g3++) {
                int k0 = ksp * 24 + g3 * 8;
                float y[8];
                #pragma unroll
                for (int u = 0; u < 8; u++) {
                    int j = k0 + u;
                    float v = 0.0f;
                    if (j < jn) {
                        int t = (t0 + j) & 255;
                        v = xb[(t << 6) + csp] * wp.A[ilo + base + j];
                    }
                    y[u] = v;
                    msum += v;
                }
                uint32_t hp[4], lp[4];
                #pragma unroll
                for (int v2 = 0; v2 < 4; v2++) {
                    float y0 = y[2 * v2], y1 = y[2 * v2 + 1];
                    uint32_t hpv = bf16pair(y0, y1);
                    float h0 = __uint_as_float(hpv << 16);
                    float h1 = __uint_as_float(hpv & 0xFFFF0000u);
                    uint32_t lpv = bf16pair(y0 - h0, y1 - h1);
                    hp[v2] = hpv;
                    lp[v2] = lpv;
                }
                sts128(hdst + g3 * 16,      hp[0], hp[1], hp[2], hp[3]);
                sts128(hdst + LH + g3 * 16, lp[0], lp[1], lp[2], lp[3]);
            }
        }
        __syncthreads();

        int nks = (jn + 15) >> 4;
        #pragma unroll 3
        for (int ks = 0; ks < nks; ks++) {
            uint32_t ko = (uint32_t)(ks << 5);
            uint32_t aH[2][4], aL[2][4];
            ldmx4(aH[0], htb + offA0 + ko);
            ldmx4(aH[1], htb + offA0 + (uint32_t)(16 * HSTB) + ko);
            ldmx4(aL[0], ltb + offA0 + ko);
            ldmx4(aL[1], ltb + offA0 + (uint32_t)(16 * HSTB) + ko);
            #pragma unroll
            for (int bt = 0; bt < 2; bt++) {
                uint32_t bo = offB0 + (uint32_t)(bt * 16 * HSTB) + ko;
                uint32_t bh[4], bl[4];
                ldmx4(bh, htb + bo);
                ldmx4(bl, ltb + bo);
                #pragma unroll
                for (int mt = 0; mt < 2; mt++) {
                    #pragma unroll
                    for (int pr = 0; pr < 2; pr++) {
                        float* Dp = D[mt][bt * 2 + pr];
                        mma_bf16(Dp, aH[mt], bh + 2 * pr);
                        mma_bf16(Dp, aH[mt], bl + 2 * pr);
                        mma_bf16(Dp, aL[mt], bh + 2 * pr);
                    }
                }
            }
        }
    }

    mpart[ksp][csp] = msum;
    __syncthreads();
    if (tid < 64) mcol[tid] = mpart[0][tid] + mpart[1][tid];
    __syncthreads();

    const float inv256 = 1.0f / 256.0f;
    if (mb == nb && tig == (g >> 1)) {
        #pragma unroll
        for (int mt = 0; mt < 2; mt++) {
            #pragma unroll
            for (int rh = 0; rh < 2; rh++) {
                int c = mb + mt * 16 + rh * 8 + g;
                int nt = mt * 2 + rh;
                int e  = (g & 1) + rh * 2;
                float m = mcol[c];
                dinv[c] = rsqrtf(D[mt][nt][e] - m * m * inv256);
            }
        }
    }
    __syncthreads();

    float* ob = out + (((size_t)(b * NWIN + w)) << 12);
    const int d0 = nb + (tig << 1);
    #pragma unroll
    for (int mt = 0; mt < 2; mt++) {
        #pragma unroll
        for (int rh = 0; rh < 2; rh++) {
            int c = mb + mt * 16 + rh * 8 + g;
            float mc = mcol[c] * inv256;
            float dc = dinv[c];
            #pragma unroll
            for (int nt = 0; nt < 4; nt++) {
                int d = d0 + nt * 8;
                float2 v;
                v.x = (D[mt][nt][rh * 2 + 0] - mc * mcol[d])     * dc * dinv[d];
                v.y = (D[mt][nt][rh * 2 + 1] - mc * mcol[d + 1]) * dc * dinv[d + 1];
                v.x = fminf(1.0f, fmaxf(-1.0f, v.x));
                v.y = fminf(1.0f, fmaxf(-1.0f, v.y));
                *(float2*)(ob + (c << 6) + d) = v;
            }
        }
    }
}

// ---------------------------------------------------------------------------
// Host: window table (alpha-independent; scale cancels in normalization).
// ---------------------------------------------------------------------------
extern "C" void kernel_launch(void* const* d_in, const int* in_sizes, int n_in,
                              void* d_out, int out_size) {
    const float* x = (const float*)d_in[0];       // (16, 256, 64) fp32
    float* out = (float*)d_out;                   // (16, 224, 64, 64) fp32

    WinParam wp;
    {
        double gw[256], P[256];
        double acc = 0.0;
        for (int t = 0; t < 256; t++) {
            double d = (double)t - 128.0;
            gw[t] = exp(-d * d);
            acc += gw[t];
            P[t] = acc;
        }
        double Ac[511];
        double mx = 0.0;
        for (int n = 0; n < 511; n++) {
            double v = 0.0;
            if (n >= 112 && n <= 398) {
                int hi = n - 112; if (hi > 255) hi = 255;
                double ph = P[hi];
                double pl = (n >= 144) ? P[n - 144] : 0.0;
                v = ph - pl;
            }
            Ac[n] = v;
            if (v > mx) mx = v;
        }
        int lo = 255, hi = 0;
        for (int t = 0; t < 256; t++) {
            double a = Ac[128 + t] / mx;
            wp.A[t] = (float)a;
            if (a > 1e-6) { if (t < lo) lo = t; if (t > hi) hi = t; }
        }
        if (hi < lo) { lo = 0; hi = 255; }
        wp.ilo  = lo;
        wp.keff = hi - lo + 1;
    }

    dim3 grid(NWIN, B_DIM);
    if (wp.keff <= 16)      corr_tmpl<1><<<grid, 256>>>(x, out, wp);
    else if (wp.keff <= 32) corr_tmpl<2><<<grid, 256>>>(x, out, wp);
    else if (wp.keff <= 48) corr_tmpl<3><<<grid, 256>>>(x, out, wp);
    else                    corr_gen<<<grid, 128>>>(x, out, wp);
}